// round 3
// baseline (speedup 1.0000x reference)
#include <cuda_runtime.h>
#include <cuda_bf16.h>
#include <float.h>

// Problem constants
#define V_   32000
#define C_   1024
#define H_   16
#define L_   8
#define F_   4096
#define B_   2
#define T_   2048
#define D_   64
#define BT_  (B_*T_)

// ---------------------------------------------------------------------------
// f32x2 packed helpers (sm_100+): one FFMA2 = 2 FMAs per lane per issue slot
// ---------------------------------------------------------------------------
__device__ __forceinline__ unsigned long long pk2(float x, float y) {
    unsigned long long r;
    asm("mov.b64 %0, {%1, %2};" : "=l"(r) : "f"(x), "f"(y));
    return r;
}
__device__ __forceinline__ void fma2(unsigned long long& c,
                                     unsigned long long a, unsigned long long b) {
    asm("fma.rn.f32x2 %0, %1, %2, %0;" : "+l"(c) : "l"(a), "l"(b));
}
__device__ __forceinline__ unsigned long long fma2v(unsigned long long a,
                                                    unsigned long long b,
                                                    unsigned long long c) {
    unsigned long long r;
    asm("fma.rn.f32x2 %0, %1, %2, %3;" : "=l"(r) : "l"(a), "l"(b), "l"(c));
    return r;
}
__device__ __forceinline__ unsigned long long mul2(unsigned long long a,
                                                   unsigned long long b) {
    unsigned long long r;
    asm("mul.rn.f32x2 %0, %1, %2;" : "=l"(r) : "l"(a), "l"(b));
    return r;
}
__device__ __forceinline__ float2 upk2(unsigned long long u) {
    float lo, hi;
    asm("mov.b64 {%0, %1}, %2;" : "=f"(lo), "=f"(hi) : "l"(u));
    return make_float2(lo, hi);
}

// ---------------------------------------------------------------------------
// Scratch (static device arrays; no allocation allowed)
// ---------------------------------------------------------------------------
__device__ float g_x  [BT_ * C_];
__device__ float g_h  [BT_ * C_];
__device__ float g_q  [BT_ * C_];
__device__ float g_k  [BT_ * C_];
__device__ float g_v  [BT_ * C_];
__device__ float g_ao [BT_ * C_];
__device__ float g_hid[BT_ * F_];
__device__ float g_xf [B_ * C_];

// ---------------------------------------------------------------------------
// Embedding
// ---------------------------------------------------------------------------
__global__ void embed_kernel(const int* __restrict__ idx,
                             const float* __restrict__ emb,
                             const float* __restrict__ pos,
                             float* __restrict__ x) {
    int row = blockIdx.x;
    int t   = row % T_;
    int tok = idx[row];
    int c   = threadIdx.x * 4;
    float4 e = *(const float4*)(emb + (size_t)tok * C_ + c);
    float4 p = *(const float4*)(pos + (size_t)t   * C_ + c);
    float4 o;
    o.x = e.x + p.x; o.y = e.y + p.y; o.z = e.z + p.z; o.w = e.w + p.w;
    *(float4*)(x + (size_t)row * C_ + c) = o;
}

// ---------------------------------------------------------------------------
// LayerNorm over C=1024. block = 256 threads, 1 row per block.
// ---------------------------------------------------------------------------
template<bool LAST>
__global__ void layernorm_kernel(const float* __restrict__ x,
                                 const float* __restrict__ g,
                                 const float* __restrict__ b,
                                 float* __restrict__ y) {
    int row_in  = LAST ? (blockIdx.x * T_ + (T_ - 1)) : blockIdx.x;
    int row_out = blockIdx.x;
    int tid = threadIdx.x;
    int c = tid * 4;

    float4 xv = *(const float4*)(x + (size_t)row_in * C_ + c);
    float s  = xv.x + xv.y + xv.z + xv.w;
    float sq = xv.x*xv.x + xv.y*xv.y + xv.z*xv.z + xv.w*xv.w;

    __shared__ float ssum[256];
    __shared__ float ssq[256];
    ssum[tid] = s; ssq[tid] = sq;
    __syncthreads();
    #pragma unroll
    for (int st = 128; st > 0; st >>= 1) {
        if (tid < st) { ssum[tid] += ssum[tid+st]; ssq[tid] += ssq[tid+st]; }
        __syncthreads();
    }
    __shared__ float s_mean, s_rstd;
    if (tid == 0) {
        float mean = ssum[0] * (1.0f / C_);
        float var  = ssq[0] * (1.0f / C_) - mean * mean;
        s_mean = mean;
        s_rstd = rsqrtf(var + 1e-5f);
    }
    __syncthreads();
    float mean = s_mean, rstd = s_rstd;

    float4 gv = *(const float4*)(g + c);
    float4 bv = *(const float4*)(b + c);
    float4 o;
    o.x = (xv.x - mean) * rstd * gv.x + bv.x;
    o.y = (xv.y - mean) * rstd * gv.y + bv.y;
    o.z = (xv.z - mean) * rstd * gv.z + bv.z;
    o.w = (xv.w - mean) * rstd * gv.w + bv.w;
    *(float4*)(y + (size_t)row_out * C_ + c) = o;
}

// ---------------------------------------------------------------------------
// SGEMM with FFMA2 (f32x2): C = A[MxK] @ B[KxN] + bias (+ReLU, +residual)
// 128x128 tile, K-slice 16, 256 threads, 8x8 per-thread microtile,
// double-buffered SMEM, A stored as duplicated pairs (a,a).
// ---------------------------------------------------------------------------
template<bool RELU, bool RES>
__global__ __launch_bounds__(256, 2)
void sgemm_kernel(const float* __restrict__ A, const float* __restrict__ B,
                  const float* __restrict__ bias, const float* __restrict__ res,
                  float* __restrict__ C, int M, int N, int K) {
    __shared__ float As[2][16][256];   // [buf][k][2m {dup pair}]
    __shared__ float Bs[2][16][128];   // [buf][k][n]

    const int tid = threadIdx.x;
    const int tx = tid & 15;        // 8 cols each
    const int ty = tid >> 4;        // 8 rows each
    const int m0 = blockIdx.y * 128;
    const int n0 = blockIdx.x * 128;

    // loader indices
    const int arow = tid >> 2;      // 0..63 (two rows: arow, arow+64)
    const int ac4  = tid & 3;       // which float4 of the 16-wide k-slice
    const int brow = tid >> 5;      // 0..7  (two rows: brow, brow+8)
    const int bc4  = tid & 31;      // which float4 of the 128-wide n-slice

    unsigned long long acc[8][4];
    #pragma unroll
    for (int i = 0; i < 8; i++)
        #pragma unroll
        for (int j = 0; j < 4; j++) acc[i][j] = 0ull;

    const int nkt = K >> 4;

    // prologue: tile 0 -> buf 0
    {
        float4 a0 = *(const float4*)(A + (size_t)(m0 + arow)      * K + ac4 * 4);
        float4 a1 = *(const float4*)(A + (size_t)(m0 + arow + 64) * K + ac4 * 4);
        float4 b0 = *(const float4*)(B + (size_t)(brow)     * N + n0 + bc4 * 4);
        float4 b1 = *(const float4*)(B + (size_t)(brow + 8) * N + n0 + bc4 * 4);
        *(float2*)&As[0][ac4*4+0][2*arow]        = make_float2(a0.x, a0.x);
        *(float2*)&As[0][ac4*4+1][2*arow]        = make_float2(a0.y, a0.y);
        *(float2*)&As[0][ac4*4+2][2*arow]        = make_float2(a0.z, a0.z);
        *(float2*)&As[0][ac4*4+3][2*arow]        = make_float2(a0.w, a0.w);
        *(float2*)&As[0][ac4*4+0][2*(arow+64)]   = make_float2(a1.x, a1.x);
        *(float2*)&As[0][ac4*4+1][2*(arow+64)]   = make_float2(a1.y, a1.y);
        *(float2*)&As[0][ac4*4+2][2*(arow+64)]   = make_float2(a1.z, a1.z);
        *(float2*)&As[0][ac4*4+3][2*(arow+64)]   = make_float2(a1.w, a1.w);
        *(float4*)&Bs[0][brow][bc4*4]     = b0;
        *(float4*)&Bs[0][brow+8][bc4*4]   = b1;
    }
    __syncthreads();

    for (int kt = 0; kt < nkt; kt++) {
        const int cur = kt & 1;
        const bool more = (kt + 1 < nkt);
        float4 na0, na1, nb0, nb1;
        if (more) {
            na0 = *(const float4*)(A + (size_t)(m0 + arow)      * K + (kt+1)*16 + ac4 * 4);
            na1 = *(const float4*)(A + (size_t)(m0 + arow + 64) * K + (kt+1)*16 + ac4 * 4);
            nb0 = *(const float4*)(B + (size_t)((kt+1)*16 + brow)     * N + n0 + bc4 * 4);
            nb1 = *(const float4*)(B + (size_t)((kt+1)*16 + brow + 8) * N + n0 + bc4 * 4);
        }

        #pragma unroll
        for (int k = 0; k < 16; k++) {
            const float* ar = &As[cur][k][ty * 16];
            float4 a0 = *(const float4*)(ar);
            float4 a1 = *(const float4*)(ar + 4);
            float4 a2 = *(const float4*)(ar + 8);
            float4 a3 = *(const float4*)(ar + 12);
            const float* br = &Bs[cur][k][tx * 8];
            float4 b0 = *(const float4*)(br);
            float4 b1 = *(const float4*)(br + 4);

            unsigned long long bu0 = pk2(b0.x, b0.y);
            unsigned long long bu1 = pk2(b0.z, b0.w);
            unsigned long long bu2 = pk2(b1.x, b1.y);
            unsigned long long bu3 = pk2(b1.z, b1.w);
            unsigned long long au[8];
            au[0] = pk2(a0.x, a0.y); au[1] = pk2(a0.z, a0.w);
            au[2] = pk2(a1.x, a1.y); au[3] = pk2(a1.z, a1.w);
            au[4] = pk2(a2.x, a2.y); au[5] = pk2(a2.z, a2.w);
            au[6] = pk2(a3.x, a3.y); au[7] = pk2(a3.z, a3.w);

            #pragma unroll
            for (int i = 0; i < 8; i++) {
                fma2(acc[i][0], au[i], bu0);
                fma2(acc[i][1], au[i], bu1);
                fma2(acc[i][2], au[i], bu2);
                fma2(acc[i][3], au[i], bu3);
            }
        }

        if (more) {
            const int nb_ = cur ^ 1;
            *(float2*)&As[nb_][ac4*4+0][2*arow]      = make_float2(na0.x, na0.x);
            *(float2*)&As[nb_][ac4*4+1][2*arow]      = make_float2(na0.y, na0.y);
            *(float2*)&As[nb_][ac4*4+2][2*arow]      = make_float2(na0.z, na0.z);
            *(float2*)&As[nb_][ac4*4+3][2*arow]      = make_float2(na0.w, na0.w);
            *(float2*)&As[nb_][ac4*4+0][2*(arow+64)] = make_float2(na1.x, na1.x);
            *(float2*)&As[nb_][ac4*4+1][2*(arow+64)] = make_float2(na1.y, na1.y);
            *(float2*)&As[nb_][ac4*4+2][2*(arow+64)] = make_float2(na1.z, na1.z);
            *(float2*)&As[nb_][ac4*4+3][2*(arow+64)] = make_float2(na1.w, na1.w);
            *(float4*)&Bs[nb_][brow][bc4*4]   = nb0;
            *(float4*)&Bs[nb_][brow+8][bc4*4] = nb1;
        }
        __syncthreads();
    }

    // epilogue
    const int nbase = n0 + tx * 8;
    float4 bias0 = *(const float4*)(bias + nbase);
    float4 bias1 = *(const float4*)(bias + nbase + 4);
    #pragma unroll
    for (int i = 0; i < 8; i++) {
        int m = m0 + ty * 8 + i;
        float2 c0 = upk2(acc[i][0]);
        float2 c1 = upk2(acc[i][1]);
        float2 c2 = upk2(acc[i][2]);
        float2 c3 = upk2(acc[i][3]);
        float4 v0, v1;
        v0.x = c0.x + bias0.x; v0.y = c0.y + bias0.y;
        v0.z = c1.x + bias0.z; v0.w = c1.y + bias0.w;
        v1.x = c2.x + bias1.x; v1.y = c2.y + bias1.y;
        v1.z = c3.x + bias1.z; v1.w = c3.y + bias1.w;
        if (RELU) {
            v0.x = fmaxf(v0.x, 0.f); v0.y = fmaxf(v0.y, 0.f);
            v0.z = fmaxf(v0.z, 0.f); v0.w = fmaxf(v0.w, 0.f);
            v1.x = fmaxf(v1.x, 0.f); v1.y = fmaxf(v1.y, 0.f);
            v1.z = fmaxf(v1.z, 0.f); v1.w = fmaxf(v1.w, 0.f);
        }
        if (RES) {
            float4 r0 = *(const float4*)(res + (size_t)m * N + nbase);
            float4 r1 = *(const float4*)(res + (size_t)m * N + nbase + 4);
            v0.x += r0.x; v0.y += r0.y; v0.z += r0.z; v0.w += r0.w;
            v1.x += r1.x; v1.y += r1.y; v1.z += r1.z; v1.w += r1.w;
        }
        *(float4*)(C + (size_t)m * N + nbase)     = v0;
        *(float4*)(C + (size_t)m * N + nbase + 4) = v1;
    }
}

// ---------------------------------------------------------------------------
// Causal flash attention, fp32 with f32x2 packed math.
// One warp per query; block = 4 warps; 32-key SMEM tiles.
// ---------------------------------------------------------------------------
__global__ __launch_bounds__(128)
void attention_kernel(const float* __restrict__ q, const float* __restrict__ k,
                      const float* __restrict__ v, float* __restrict__ o) {
    __shared__ float Ks[32][68];   // padded rows
    __shared__ float Vs[32][68];

    const int b  = blockIdx.z;
    const int h  = blockIdx.y;
    const int t0 = blockIdx.x * 4;
    const int w    = threadIdx.x >> 5;
    const int lane = threadIdx.x & 31;
    const int t = t0 + w;

    // load q row (scaled), pack into 32 f32x2 pairs
    const float* qp = q + ((size_t)(b * T_ + t) * C_ + h * D_);
    unsigned long long qu[32];
    #pragma unroll
    for (int i = 0; i < 16; i++) {
        float4 qv = *(const float4*)(qp + i * 4);
        qu[2*i + 0] = pk2(qv.x * 0.125f, qv.y * 0.125f);
        qu[2*i + 1] = pk2(qv.z * 0.125f, qv.w * 0.125f);
    }

    unsigned long long o2[32];
    #pragma unroll
    for (int i = 0; i < 32; i++) o2[i] = 0ull;
    float m = -FLT_MAX, l = 0.0f;

    const int nkb = (t0 + 3) / 32 + 1;
    const size_t kv_head_off = (size_t)h * D_;

    for (int kb = 0; kb < nkb; kb++) {
        __syncthreads();
        #pragma unroll
        for (int r = 0; r < 4; r++) {
            int idx  = threadIdx.x + r * 128;   // 0..511
            int key  = idx >> 4;                // 0..31
            int c4   = idx & 15;                // 0..15
            size_t goff = (size_t)(b * T_ + kb * 32 + key) * C_ + kv_head_off + c4 * 4;
            *(float4*)&Ks[key][c4 * 4] = *(const float4*)(k + goff);
            *(float4*)&Vs[key][c4 * 4] = *(const float4*)(v + goff);
        }
        __syncthreads();

        // score for this lane's key (packed dot product)
        unsigned long long s2 = 0ull;
        #pragma unroll
        for (int i = 0; i < 16; i++) {
            float4 kk = *(float4*)&Ks[lane][i * 4];
            fma2(s2, qu[2*i + 0], pk2(kk.x, kk.y));
            fma2(s2, qu[2*i + 1], pk2(kk.z, kk.w));
        }
        float2 sp = upk2(s2);
        float s = sp.x + sp.y;

        int kidx = kb * 32 + lane;
        bool masked = (kidx > t);
        if (masked) s = -FLT_MAX;

        float mloc = s;
        #pragma unroll
        for (int off = 16; off; off >>= 1)
            mloc = fmaxf(mloc, __shfl_xor_sync(0xffffffffu, mloc, off));
        float mnew = fmaxf(m, mloc);
        float alpha = __expf(m - mnew);
        float p = masked ? 0.0f : __expf(s - mnew);

        float psum = p;
        #pragma unroll
        for (int off = 16; off; off >>= 1)
            psum += __shfl_xor_sync(0xffffffffu, psum, off);

        l = l * alpha + psum;
        m = mnew;

        unsigned long long pa = pk2(p, p);
        unsigned long long al = pk2(alpha, alpha);
        #pragma unroll
        for (int i = 0; i < 16; i++) {
            float4 vv = *(float4*)&Vs[lane][i * 4];
            o2[2*i + 0] = fma2v(o2[2*i + 0], al, mul2(pa, pk2(vv.x, vv.y)));
            o2[2*i + 1] = fma2v(o2[2*i + 1], al, mul2(pa, pk2(vv.z, vv.w)));
        }
    }

    // unpack and butterfly-reduce across lanes
    float orf[64];
    #pragma unroll
    for (int i = 0; i < 32; i++) {
        float2 f = upk2(o2[i]);
        orf[2*i] = f.x; orf[2*i + 1] = f.y;
    }
    #pragma unroll
    for (int i = 0; i < 64; i++) {
        #pragma unroll
        for (int off = 16; off; off >>= 1)
            orf[i] += __shfl_xor_sync(0xffffffffu, orf[i], off);
    }
    if (lane == 0) {
        float inv = 1.0f / l;
        float* op = o + ((size_t)(b * T_ + t) * C_ + h * D_);
        #pragma unroll
        for (int i = 0; i < 16; i++) {
            float4 ov;
            ov.x = orf[4*i + 0] * inv; ov.y = orf[4*i + 1] * inv;
            ov.z = orf[4*i + 2] * inv; ov.w = orf[4*i + 3] * inv;
            *(float4*)(op + i * 4) = ov;
        }
    }
}

// ---------------------------------------------------------------------------
// Logits: out[b,v] = dot(xf[b,:], W[:,v]) + out_b[v]
// ---------------------------------------------------------------------------
__global__ void logits_kernel(const float* __restrict__ xf,
                              const float* __restrict__ W,
                              const float* __restrict__ bias,
                              float* __restrict__ out) {
    __shared__ float xs[C_];
    const int b = blockIdx.y;
    const int tid = threadIdx.x;
    #pragma unroll
    for (int r = 0; r < C_ / 128; r++)
        xs[tid + r * 128] = xf[b * C_ + tid + r * 128];
    __syncthreads();

    int vcol = blockIdx.x * 128 + tid;
    float acc = bias[vcol];
    const float* wp = W + vcol;
    #pragma unroll 8
    for (int k = 0; k < C_; k++)
        acc = fmaf(xs[k], wp[(size_t)k * V_], acc);
    out[(size_t)b * V_ + vcol] = acc;
}

// ---------------------------------------------------------------------------
// Launch
// ---------------------------------------------------------------------------
extern "C" void kernel_launch(void* const* d_in, const int* in_sizes, int n_in,
                              void* d_out, int out_size) {
    const int*   idx   = (const int*)  d_in[0];
    const float* emb   = (const float*)d_in[1];
    const float* pos   = (const float*)d_in[2];
    const float* ln1_g = (const float*)d_in[3];
    const float* ln1_b = (const float*)d_in[4];
    const float* wq    = (const float*)d_in[5];
    const float* bq    = (const float*)d_in[6];
    const float* wk    = (const float*)d_in[7];
    const float* bk    = (const float*)d_in[8];
    const float* wv    = (const float*)d_in[9];
    const float* bv    = (const float*)d_in[10];
    const float* wo    = (const float*)d_in[11];
    const float* bo    = (const float*)d_in[12];
    const float* ln2_g = (const float*)d_in[13];
    const float* ln2_b = (const float*)d_in[14];
    const float* w1    = (const float*)d_in[15];
    const float* b1    = (const float*)d_in[16];
    const float* w2    = (const float*)d_in[17];
    const float* b2    = (const float*)d_in[18];
    const float* lnf_g = (const float*)d_in[19];
    const float* lnf_b = (const float*)d_in[20];
    const float* out_w = (const float*)d_in[21];
    const float* out_b = (const float*)d_in[22];
    float* out = (float*)d_out;

    float *x, *h, *q, *k, *v, *ao, *hid, *xf;
    cudaGetSymbolAddress((void**)&x,   g_x);
    cudaGetSymbolAddress((void**)&h,   g_h);
    cudaGetSymbolAddress((void**)&q,   g_q);
    cudaGetSymbolAddress((void**)&k,   g_k);
    cudaGetSymbolAddress((void**)&v,   g_v);
    cudaGetSymbolAddress((void**)&ao,  g_ao);
    cudaGetSymbolAddress((void**)&hid, g_hid);
    cudaGetSymbolAddress((void**)&xf,  g_xf);

    embed_kernel<<<BT_, 256>>>(idx, emb, pos, x);

    dim3 gemm_cc(C_ / 128, BT_ / 128);   // (8, 32)
    dim3 gemm_cf(F_ / 128, BT_ / 128);   // (32, 32)
    dim3 attn_grid(T_ / 4, H_, B_);      // (512, 16, 2)

    for (int l = 0; l < L_; l++) {
        layernorm_kernel<false><<<BT_, 256>>>(x, ln1_g + l * C_, ln1_b + l * C_, h);

        sgemm_kernel<false, false><<<gemm_cc, 256>>>(h, wq + (size_t)l * C_ * C_, bq + l * C_, nullptr, q, BT_, C_, C_);
        sgemm_kernel<false, false><<<gemm_cc, 256>>>(h, wk + (size_t)l * C_ * C_, bk + l * C_, nullptr, k, BT_, C_, C_);
        sgemm_kernel<false, false><<<gemm_cc, 256>>>(h, wv + (size_t)l * C_ * C_, bv + l * C_, nullptr, v, BT_, C_, C_);

        attention_kernel<<<attn_grid, 128>>>(q, k, v, ao);

        // x = x + (ao @ wo + bo)
        sgemm_kernel<false, true><<<gemm_cc, 256>>>(ao, wo + (size_t)l * C_ * C_, bo + l * C_, x, x, BT_, C_, C_);

        layernorm_kernel<false><<<BT_, 256>>>(x, ln2_g + l * C_, ln2_b + l * C_, h);

        // hid = relu(h @ w1 + b1)
        sgemm_kernel<true, false><<<gemm_cf, 256>>>(h, w1 + (size_t)l * C_ * F_, b1 + l * F_, nullptr, hid, BT_, F_, C_);
        // x = x + (hid @ w2 + b2)
        sgemm_kernel<false, true><<<gemm_cc, 256>>>(hid, w2 + (size_t)l * F_ * C_, b2 + l * C_, x, x, BT_, C_, F_);
    }

    layernorm_kernel<true><<<B_, 256>>>(x, lnf_g, lnf_b, xf);
    logits_kernel<<<dim3(V_ / 128, B_), 128>>>(xf, out_w, out_b, out);
}

// round 5
// speedup vs baseline: 1.9409x; 1.9409x over previous
#include <cuda_runtime.h>
#include <cuda_bf16.h>
#include <float.h>
#include <cstdint>

// Problem constants
#define V_   32000
#define C_   1024
#define H_   16
#define L_   8
#define F_   4096
#define B_   2
#define T_   2048
#define D_   64
#define BT_  (B_*T_)

// ===========================================================================
// helpers
// ===========================================================================
__device__ __forceinline__ uint32_t smem_u32(const void* p) {
    uint32_t a;
    asm("{ .reg .u64 t; cvta.to.shared.u64 t, %1; cvt.u32.u64 %0, t; }"
        : "=r"(a) : "l"(p));
    return a;
}

#define CP_ASYNC16(saddr, gptr) \
    asm volatile("cp.async.cg.shared.global [%0], [%1], 16;" \
                 :: "r"(saddr), "l"(gptr) : "memory")
#define CP_COMMIT() asm volatile("cp.async.commit_group;" ::: "memory")
#define CP_WAIT1()  asm volatile("cp.async.wait_group 1;" ::: "memory")
#define CP_WAIT0()  asm volatile("cp.async.wait_group 0;" ::: "memory")

__device__ __forceinline__ void ldm_x4(uint32_t addr, uint32_t& r0, uint32_t& r1,
                                       uint32_t& r2, uint32_t& r3) {
    asm volatile("ldmatrix.sync.aligned.m8n8.x4.shared.b16 {%0,%1,%2,%3}, [%4];"
                 : "=r"(r0), "=r"(r1), "=r"(r2), "=r"(r3) : "r"(addr));
}

__device__ __forceinline__ void mma_bf16(float& d0, float& d1, float& d2, float& d3,
                                         uint32_t a0, uint32_t a1, uint32_t a2, uint32_t a3,
                                         uint32_t b0, uint32_t b1) {
    asm volatile(
        "mma.sync.aligned.m16n8k16.row.col.f32.bf16.bf16.f32 "
        "{%0,%1,%2,%3}, {%4,%5,%6,%7}, {%8,%9}, {%0,%1,%2,%3};"
        : "+f"(d0), "+f"(d1), "+f"(d2), "+f"(d3)
        : "r"(a0), "r"(a1), "r"(a2), "r"(a3), "r"(b0), "r"(b1));
}

// bf16 hi/lo split helpers
__device__ __forceinline__ void split1(float v, __nv_bfloat16& h, __nv_bfloat16& l) {
    h = __float2bfloat16(v);
    l = __float2bfloat16(v - __bfloat162float(h));
}
__device__ __forceinline__ void split2_store(float x, float y,
                                             __nv_bfloat16* ph, __nv_bfloat16* pl) {
    __nv_bfloat16 h0, h1, l0, l1;
    split1(x, h0, l0); split1(y, h1, l1);
    __nv_bfloat162 H; H.x = h0; H.y = h1;
    __nv_bfloat162 L; L.x = l0; L.y = l1;
    *(__nv_bfloat162*)ph = H;
    *(__nv_bfloat162*)pl = L;
}
__device__ __forceinline__ void split4_store(float4 v, __nv_bfloat16* ph, __nv_bfloat16* pl) {
    split2_store(v.x, v.y, ph, pl);
    split2_store(v.z, v.w, ph + 2, pl + 2);
}

// ===========================================================================
// Scratch (static device arrays)
// ===========================================================================
__device__ float g_x  [BT_ * C_];
__device__ float g_q  [BT_ * C_];
__device__ float g_k  [BT_ * C_];
__device__ float g_v  [BT_ * C_];
__device__ float g_xf [B_ * C_];

__device__ __nv_bfloat16 g_h_h  [BT_ * C_];
__device__ __nv_bfloat16 g_h_l  [BT_ * C_];
__device__ __nv_bfloat16 g_ao_h [BT_ * C_];
__device__ __nv_bfloat16 g_ao_l [BT_ * C_];
__device__ __nv_bfloat16 g_hid_h[BT_ * F_];
__device__ __nv_bfloat16 g_hid_l[BT_ * F_];

// transposed+split weights [N,K] bf16
__device__ __nv_bfloat16 g_wqT_h[L_ * C_ * C_];
__device__ __nv_bfloat16 g_wqT_l[L_ * C_ * C_];
__device__ __nv_bfloat16 g_wkT_h[L_ * C_ * C_];
__device__ __nv_bfloat16 g_wkT_l[L_ * C_ * C_];
__device__ __nv_bfloat16 g_wvT_h[L_ * C_ * C_];
__device__ __nv_bfloat16 g_wvT_l[L_ * C_ * C_];
__device__ __nv_bfloat16 g_woT_h[L_ * C_ * C_];
__device__ __nv_bfloat16 g_woT_l[L_ * C_ * C_];
__device__ __nv_bfloat16 g_w1T_h[L_ * C_ * F_];
__device__ __nv_bfloat16 g_w1T_l[L_ * C_ * F_];
__device__ __nv_bfloat16 g_w2T_h[L_ * F_ * C_];
__device__ __nv_bfloat16 g_w2T_l[L_ * F_ * C_];

// ===========================================================================
// Embedding
// ===========================================================================
__global__ void embed_kernel(const int* __restrict__ idx,
                             const float* __restrict__ emb,
                             const float* __restrict__ pos,
                             float* __restrict__ x) {
    int row = blockIdx.x;
    int t   = row % T_;
    int tok = idx[row];
    int c   = threadIdx.x * 4;
    float4 e = *(const float4*)(emb + (size_t)tok * C_ + c);
    float4 p = *(const float4*)(pos + (size_t)t   * C_ + c);
    float4 o;
    o.x = e.x + p.x; o.y = e.y + p.y; o.z = e.z + p.z; o.w = e.w + p.w;
    *(float4*)(x + (size_t)row * C_ + c) = o;
}

// ===========================================================================
// Weight transpose + bf16 split: in [K,N] fp32 (per layer) -> out [N,K] hi/lo
// ===========================================================================
__global__ void transpose_split_kernel(const float* __restrict__ in,
                                       __nv_bfloat16* __restrict__ oh,
                                       __nv_bfloat16* __restrict__ ol,
                                       int K, int N) {
    __shared__ float t[32][33];
    const size_t lbase = (size_t)blockIdx.z * K * N;
    const float* inl = in + lbase;
    const int k0 = blockIdx.y * 32;
    const int n0 = blockIdx.x * 32;
    #pragma unroll
    for (int j = 0; j < 4; j++) {
        int k = k0 + threadIdx.y + j * 8;
        t[threadIdx.y + j * 8][threadIdx.x] = inl[(size_t)k * N + n0 + threadIdx.x];
    }
    __syncthreads();
    #pragma unroll
    for (int j = 0; j < 4; j++) {
        int n = n0 + threadIdx.y + j * 8;
        float v = t[threadIdx.x][threadIdx.y + j * 8];
        __nv_bfloat16 h, l;
        split1(v, h, l);
        size_t off = lbase + (size_t)n * K + k0 + threadIdx.x;
        oh[off] = h;
        ol[off] = l;
    }
}

// ===========================================================================
// LayerNorm, bf16 hi/lo output. 1 row/block, 256 threads.
// ===========================================================================
__global__ void layernorm_bf16_kernel(const float* __restrict__ x,
                                      const float* __restrict__ g,
                                      const float* __restrict__ b,
                                      __nv_bfloat16* __restrict__ yh,
                                      __nv_bfloat16* __restrict__ yl) {
    int row = blockIdx.x;
    int tid = threadIdx.x;
    int c = tid * 4;

    float4 xv = *(const float4*)(x + (size_t)row * C_ + c);
    float s  = xv.x + xv.y + xv.z + xv.w;
    float sq = xv.x*xv.x + xv.y*xv.y + xv.z*xv.z + xv.w*xv.w;

    __shared__ float ssum[256];
    __shared__ float ssq[256];
    ssum[tid] = s; ssq[tid] = sq;
    __syncthreads();
    #pragma unroll
    for (int st = 128; st > 0; st >>= 1) {
        if (tid < st) { ssum[tid] += ssum[tid+st]; ssq[tid] += ssq[tid+st]; }
        __syncthreads();
    }
    __shared__ float s_mean, s_rstd;
    if (tid == 0) {
        float mean = ssum[0] * (1.0f / C_);
        float var  = ssq[0] * (1.0f / C_) - mean * mean;
        s_mean = mean;
        s_rstd = rsqrtf(var + 1e-5f);
    }
    __syncthreads();
    float mean = s_mean, rstd = s_rstd;

    float4 gv = *(const float4*)(g + c);
    float4 bv = *(const float4*)(b + c);
    float4 o;
    o.x = (xv.x - mean) * rstd * gv.x + bv.x;
    o.y = (xv.y - mean) * rstd * gv.y + bv.y;
    o.z = (xv.z - mean) * rstd * gv.z + bv.z;
    o.w = (xv.w - mean) * rstd * gv.w + bv.w;
    split4_store(o, yh + (size_t)row * C_ + c, yl + (size_t)row * C_ + c);
}

// Final LayerNorm (last token), fp32 output
__global__ void layernorm_last_kernel(const float* __restrict__ x,
                                      const float* __restrict__ g,
                                      const float* __restrict__ b,
                                      float* __restrict__ y) {
    int row_in  = blockIdx.x * T_ + (T_ - 1);
    int tid = threadIdx.x;
    int c = tid * 4;

    float4 xv = *(const float4*)(x + (size_t)row_in * C_ + c);
    float s  = xv.x + xv.y + xv.z + xv.w;
    float sq = xv.x*xv.x + xv.y*xv.y + xv.z*xv.z + xv.w*xv.w;

    __shared__ float ssum[256];
    __shared__ float ssq[256];
    ssum[tid] = s; ssq[tid] = sq;
    __syncthreads();
    #pragma unroll
    for (int st = 128; st > 0; st >>= 1) {
        if (tid < st) { ssum[tid] += ssum[tid+st]; ssq[tid] += ssq[tid+st]; }
        __syncthreads();
    }
    __shared__ float s_mean, s_rstd;
    if (tid == 0) {
        float mean = ssum[0] * (1.0f / C_);
        float var  = ssq[0] * (1.0f / C_) - mean * mean;
        s_mean = mean;
        s_rstd = rsqrtf(var + 1e-5f);
    }
    __syncthreads();
    float mean = s_mean, rstd = s_rstd;

    float4 gv = *(const float4*)(g + c);
    float4 bv = *(const float4*)(b + c);
    float4 o;
    o.x = (xv.x - mean) * rstd * gv.x + bv.x;
    o.y = (xv.y - mean) * rstd * gv.y + bv.y;
    o.z = (xv.z - mean) * rstd * gv.z + bv.z;
    o.w = (xv.w - mean) * rstd * gv.w + bv.w;
    *(float4*)(y + (size_t)blockIdx.x * C_ + c) = o;
}

// ===========================================================================
// mma.sync split-bf16 GEMM.
// C[M,N] = (Ah+Al)[M,K] @ (Bh+Bl)[N,K]^T (3-term) + bias (+ReLU / +res)
// 128x128 CTA tile, BK=64, 8 warps (2x4), warp tile 64x32.
// SW128-swizzled SMEM, cp.async 2-stage pipeline.
// ===========================================================================
#define SWZ(row, chunk) ((((chunk) ^ ((row) & 7)) << 4) + (row) * 128)
#define TILE_BYTES   16384            // 128 rows x 128B
#define STAGE_BYTES  (4 * TILE_BYTES) // Ah, Al, Bh, Bl
#define GEMM_SMEM    (2 * STAGE_BYTES)

// load one 128x64 bf16 tile into swizzled SMEM via cp.async (per-thread 4 chunks)
__device__ __forceinline__ void load_tile_cp(const __nv_bfloat16* __restrict__ src,
                                             int row0, int K, int kt,
                                             uint32_t sbase, int tid) {
    #pragma unroll
    for (int r = 0; r < 4; r++) {
        int cid = tid + r * 256;      // 0..1023
        int row = cid >> 3;           // 0..127
        int c   = cid & 7;            // 16B chunk in row
        const __nv_bfloat16* g = src + (size_t)(row0 + row) * K + kt * 64 + c * 8;
        CP_ASYNC16(sbase + SWZ(row, c), g);
    }
}

template<bool RELU, bool RES, bool OUTBF16>
__global__ __launch_bounds__(256, 1)
void gemm_tc(const __nv_bfloat16* __restrict__ Ah, const __nv_bfloat16* __restrict__ Al,
             const __nv_bfloat16* __restrict__ Bh, const __nv_bfloat16* __restrict__ Bl,
             const float* __restrict__ bias, const float* __restrict__ res,
             float* __restrict__ Cf,
             __nv_bfloat16* __restrict__ Ch, __nv_bfloat16* __restrict__ Cl,
             int M, int N, int K) {
    extern __shared__ char dsm[];
    const uint32_t base = smem_u32(dsm);

    const int tid  = threadIdx.x;
    const int wid  = tid >> 5;
    const int lane = tid & 31;
    const int m0 = blockIdx.y * 128;
    const int n0 = blockIdx.x * 128;
    const int wm = wid & 1;           // 0..1 -> 64-row block
    const int wn = wid >> 1;          // 0..3 -> 32-col block

    float acc[4][4][4];
    #pragma unroll
    for (int i = 0; i < 4; i++)
        #pragma unroll
        for (int j = 0; j < 4; j++)
            #pragma unroll
            for (int r = 0; r < 4; r++) acc[i][j][r] = 0.0f;

    const int nkt = K >> 6;

    // ldmatrix lane-row assignments (constant per thread)
    const int a_row  = wm * 64 + (lane & 15);          // + mi*16
    const int a_csel = lane >> 4;                       // chunk half
    const int b_row  = wn * 32 + ((lane & 7) | ((lane & 16) >> 1)); // + nj*16
    const int b_csel = (lane >> 3) & 1;

    // prologue
    load_tile_cp(Ah, m0, K, 0, base,                   tid);
    load_tile_cp(Al, m0, K, 0, base + TILE_BYTES,      tid);
    load_tile_cp(Bh, n0, K, 0, base + 2 * TILE_BYTES,  tid);
    load_tile_cp(Bl, n0, K, 0, base + 3 * TILE_BYTES,  tid);
    CP_COMMIT();
    if (nkt > 1) {
        load_tile_cp(Ah, m0, K, 1, base + STAGE_BYTES,                  tid);
        load_tile_cp(Al, m0, K, 1, base + STAGE_BYTES + TILE_BYTES,     tid);
        load_tile_cp(Bh, n0, K, 1, base + STAGE_BYTES + 2 * TILE_BYTES, tid);
        load_tile_cp(Bl, n0, K, 1, base + STAGE_BYTES + 3 * TILE_BYTES, tid);
        CP_COMMIT();
    }

    for (int kt = 0; kt < nkt; kt++) {
        if (kt + 1 < nkt) { CP_WAIT1(); } else { CP_WAIT0(); }
        __syncthreads();

        const uint32_t sb  = base + (kt & 1) * STAGE_BYTES;
        const uint32_t sAh = sb;
        const uint32_t sAl = sb + TILE_BYTES;
        const uint32_t sBh = sb + 2 * TILE_BYTES;
        const uint32_t sBl = sb + 3 * TILE_BYTES;

        #pragma unroll
        for (int ks = 0; ks < 4; ks++) {
            const int ac = ks * 2 + a_csel;
            const int bc = ks * 2 + b_csel;
            uint32_t ah[4][4], al[4][4];
            #pragma unroll
            for (int mi = 0; mi < 4; mi++) {
                int row = a_row + mi * 16;
                ldm_x4(sAh + SWZ(row, ac), ah[mi][0], ah[mi][1], ah[mi][2], ah[mi][3]);
                ldm_x4(sAl + SWZ(row, ac), al[mi][0], al[mi][1], al[mi][2], al[mi][3]);
            }
            uint32_t bh[4][2], bl[4][2];
            #pragma unroll
            for (int nj = 0; nj < 2; nj++) {
                int row = b_row + nj * 16;
                ldm_x4(sBh + SWZ(row, bc), bh[nj*2][0], bh[nj*2][1], bh[nj*2+1][0], bh[nj*2+1][1]);
                ldm_x4(sBl + SWZ(row, bc), bl[nj*2][0], bl[nj*2][1], bl[nj*2+1][0], bl[nj*2+1][1]);
            }
            #pragma unroll
            for (int mi = 0; mi < 4; mi++) {
                #pragma unroll
                for (int ni = 0; ni < 4; ni++) {
                    mma_bf16(acc[mi][ni][0], acc[mi][ni][1], acc[mi][ni][2], acc[mi][ni][3],
                             ah[mi][0], ah[mi][1], ah[mi][2], ah[mi][3],
                             bh[ni][0], bh[ni][1]);
                    mma_bf16(acc[mi][ni][0], acc[mi][ni][1], acc[mi][ni][2], acc[mi][ni][3],
                             ah[mi][0], ah[mi][1], ah[mi][2], ah[mi][3],
                             bl[ni][0], bl[ni][1]);
                    mma_bf16(acc[mi][ni][0], acc[mi][ni][1], acc[mi][ni][2], acc[mi][ni][3],
                             al[mi][0], al[mi][1], al[mi][2], al[mi][3],
                             bh[ni][0], bh[ni][1]);
                }
            }
        }
        __syncthreads();
        if (kt + 2 < nkt) {
            const uint32_t nb = base + (kt & 1) * STAGE_BYTES;
            load_tile_cp(Ah, m0, K, kt + 2, nb,                  tid);
            load_tile_cp(Al, m0, K, kt + 2, nb + TILE_BYTES,     tid);
            load_tile_cp(Bh, n0, K, kt + 2, nb + 2 * TILE_BYTES, tid);
            load_tile_cp(Bl, n0, K, kt + 2, nb + 3 * TILE_BYTES, tid);
            CP_COMMIT();
        }
    }

    // epilogue
    const int qm = lane >> 2;          // 0..7
    const int qn = (lane & 3) * 2;     // 0,2,4,6
    #pragma unroll
    for (int mi = 0; mi < 4; mi++) {
        #pragma unroll
        for (int ni = 0; ni < 4; ni++) {
            const int n = n0 + wn * 32 + ni * 8 + qn;
            float2 bv = *(const float2*)(bias + n);
            #pragma unroll
            for (int half = 0; half < 2; half++) {
                const int m = m0 + wm * 64 + mi * 16 + qm + half * 8;
                float vx = acc[mi][ni][half*2 + 0] + bv.x;
                float vy = acc[mi][ni][half*2 + 1] + bv.y;
                if (RELU) { vx = fmaxf(vx, 0.f); vy = fmaxf(vy, 0.f); }
                if (RES) {
                    float2 rv = *(const float2*)(res + (size_t)m * N + n);
                    vx += rv.x; vy += rv.y;
                }
                if (OUTBF16) {
                    split2_store(vx, vy, Ch + (size_t)m * N + n, Cl + (size_t)m * N + n);
                } else {
                    *(float2*)(Cf + (size_t)m * N + n) = make_float2(vx, vy);
                }
            }
        }
    }
}

// ===========================================================================
// Causal flash attention, fp32, bf16 hi/lo output.
// ===========================================================================
__global__ __launch_bounds__(128)
void attention_kernel(const float* __restrict__ q, const float* __restrict__ k,
                      const float* __restrict__ v,
                      __nv_bfloat16* __restrict__ aoh,
                      __nv_bfloat16* __restrict__ aol) {
    __shared__ float Ks[32][68];
    __shared__ float Vs[32][68];

    const int b  = blockIdx.z;
    const int h  = blockIdx.y;
    const int t0 = blockIdx.x * 4;
    const int w    = threadIdx.x >> 5;
    const int lane = threadIdx.x & 31;
    const int t = t0 + w;

    const float* qp = q + ((size_t)(b * T_ + t) * C_ + h * D_);
    float4 qr[16];
    #pragma unroll
    for (int i = 0; i < 16; i++) {
        float4 qv = *(const float4*)(qp + i * 4);
        qr[i].x = qv.x * 0.125f; qr[i].y = qv.y * 0.125f;
        qr[i].z = qv.z * 0.125f; qr[i].w = qv.w * 0.125f;
    }

    float4 orr[16];
    #pragma unroll
    for (int i = 0; i < 16; i++) orr[i] = make_float4(0.f, 0.f, 0.f, 0.f);
    float m = -FLT_MAX, l = 0.0f;

    const int nkb = (t0 + 3) / 32 + 1;
    const size_t kv_head_off = (size_t)h * D_;

    for (int kb = 0; kb < nkb; kb++) {
        __syncthreads();
        #pragma unroll
        for (int r = 0; r < 4; r++) {
            int idx  = threadIdx.x + r * 128;
            int key  = idx >> 4;
            int c4   = idx & 15;
            size_t goff = (size_t)(b * T_ + kb * 32 + key) * C_ + kv_head_off + c4 * 4;
            *(float4*)&Ks[key][c4 * 4] = *(const float4*)(k + goff);
            *(float4*)&Vs[key][c4 * 4] = *(const float4*)(v + goff);
        }
        __syncthreads();

        float s = 0.0f;
        #pragma unroll
        for (int i = 0; i < 16; i++) {
            float4 kk = *(float4*)&Ks[lane][i * 4];
            s = fmaf(qr[i].x, kk.x, s);
            s = fmaf(qr[i].y, kk.y, s);
            s = fmaf(qr[i].z, kk.z, s);
            s = fmaf(qr[i].w, kk.w, s);
        }
        int kidx = kb * 32 + lane;
        bool masked = (kidx > t);
        if (masked) s = -FLT_MAX;

        float mloc = s;
        #pragma unroll
        for (int off = 16; off; off >>= 1)
            mloc = fmaxf(mloc, __shfl_xor_sync(0xffffffffu, mloc, off));
        float mnew = fmaxf(m, mloc);
        float alpha = __expf(m - mnew);
        float p = masked ? 0.0f : __expf(s - mnew);

        float psum = p;
        #pragma unroll
        for (int off = 16; off; off >>= 1)
            psum += __shfl_xor_sync(0xffffffffu, psum, off);

        l = l * alpha + psum;
        m = mnew;

        #pragma unroll
        for (int i = 0; i < 16; i++) {
            float4 vv = *(float4*)&Vs[lane][i * 4];
            orr[i].x = fmaf(p, vv.x, orr[i].x * alpha);
            orr[i].y = fmaf(p, vv.y, orr[i].y * alpha);
            orr[i].z = fmaf(p, vv.z, orr[i].z * alpha);
            orr[i].w = fmaf(p, vv.w, orr[i].w * alpha);
        }
    }

    #pragma unroll
    for (int i = 0; i < 16; i++) {
        #pragma unroll
        for (int off = 16; off; off >>= 1) {
            orr[i].x += __shfl_xor_sync(0xffffffffu, orr[i].x, off);
            orr[i].y += __shfl_xor_sync(0xffffffffu, orr[i].y, off);
            orr[i].z += __shfl_xor_sync(0xffffffffu, orr[i].z, off);
            orr[i].w += __shfl_xor_sync(0xffffffffu, orr[i].w, off);
        }
    }
    if (lane == 0) {
        float inv = 1.0f / l;
        size_t obase = (size_t)(b * T_ + t) * C_ + h * D_;
        #pragma unroll
        for (int i = 0; i < 16; i++) {
            float4 ov;
            ov.x = orr[i].x * inv; ov.y = orr[i].y * inv;
            ov.z = orr[i].z * inv; ov.w = orr[i].w * inv;
            split4_store(ov, aoh + obase + i * 4, aol + obase + i * 4);
        }
    }
}

// ===========================================================================
// Logits
// ===========================================================================
__global__ void logits_kernel(const float* __restrict__ xf,
                              const float* __restrict__ W,
                              const float* __restrict__ bias,
                              float* __restrict__ out) {
    __shared__ float xs[C_];
    const int b = blockIdx.y;
    const int tid = threadIdx.x;
    #pragma unroll
    for (int r = 0; r < C_ / 128; r++)
        xs[tid + r * 128] = xf[b * C_ + tid + r * 128];
    __syncthreads();

    int vcol = blockIdx.x * 128 + tid;
    float acc = bias[vcol];
    const float* wp = W + vcol;
    #pragma unroll 8
    for (int k = 0; k < C_; k++)
        acc = fmaf(xs[k], wp[(size_t)k * V_], acc);
    out[(size_t)b * V_ + vcol] = acc;
}

// ===========================================================================
// Launch
// ===========================================================================
extern "C" void kernel_launch(void* const* d_in, const int* in_sizes, int n_in,
                              void* d_out, int out_size) {
    const int*   idx   = (const int*)  d_in[0];
    const float* emb   = (const float*)d_in[1];
    const float* pos   = (const float*)d_in[2];
    const float* ln1_g = (const float*)d_in[3];
    const float* ln1_b = (const float*)d_in[4];
    const float* wq    = (const float*)d_in[5];
    const float* bq    = (const float*)d_in[6];
    const float* wk    = (const float*)d_in[7];
    const float* bk    = (const float*)d_in[8];
    const float* wv    = (const float*)d_in[9];
    const float* bv    = (const float*)d_in[10];
    const float* wo    = (const float*)d_in[11];
    const float* bo    = (const float*)d_in[12];
    const float* ln2_g = (const float*)d_in[13];
    const float* ln2_b = (const float*)d_in[14];
    const float* w1    = (const float*)d_in[15];
    const float* b1    = (const float*)d_in[16];
    const float* w2    = (const float*)d_in[17];
    const float* b2    = (const float*)d_in[18];
    const float* lnf_g = (const float*)d_in[19];
    const float* lnf_b = (const float*)d_in[20];
    const float* out_w = (const float*)d_in[21];
    const float* out_b = (const float*)d_in[22];
    float* out = (float*)d_out;

    float *x, *q, *k, *v, *xf;
    cudaGetSymbolAddress((void**)&x,  g_x);
    cudaGetSymbolAddress((void**)&q,  g_q);
    cudaGetSymbolAddress((void**)&k,  g_k);
    cudaGetSymbolAddress((void**)&v,  g_v);
    cudaGetSymbolAddress((void**)&xf, g_xf);

    __nv_bfloat16 *h_h, *h_l, *ao_h, *ao_l, *hid_h, *hid_l;
    cudaGetSymbolAddress((void**)&h_h,   g_h_h);
    cudaGetSymbolAddress((void**)&h_l,   g_h_l);
    cudaGetSymbolAddress((void**)&ao_h,  g_ao_h);
    cudaGetSymbolAddress((void**)&ao_l,  g_ao_l);
    cudaGetSymbolAddress((void**)&hid_h, g_hid_h);
    cudaGetSymbolAddress((void**)&hid_l, g_hid_l);

    __nv_bfloat16 *wqT_h, *wqT_l, *wkT_h, *wkT_l, *wvT_h, *wvT_l, *woT_h, *woT_l;
    __nv_bfloat16 *w1T_h, *w1T_l, *w2T_h, *w2T_l;
    cudaGetSymbolAddress((void**)&wqT_h, g_wqT_h);
    cudaGetSymbolAddress((void**)&wqT_l, g_wqT_l);
    cudaGetSymbolAddress((void**)&wkT_h, g_wkT_h);
    cudaGetSymbolAddress((void**)&wkT_l, g_wkT_l);
    cudaGetSymbolAddress((void**)&wvT_h, g_wvT_h);
    cudaGetSymbolAddress((void**)&wvT_l, g_wvT_l);
    cudaGetSymbolAddress((void**)&woT_h, g_woT_h);
    cudaGetSymbolAddress((void**)&woT_l, g_woT_l);
    cudaGetSymbolAddress((void**)&w1T_h, g_w1T_h);
    cudaGetSymbolAddress((void**)&w1T_l, g_w1T_l);
    cudaGetSymbolAddress((void**)&w2T_h, g_w2T_h);
    cudaGetSymbolAddress((void**)&w2T_l, g_w2T_l);

    cudaFuncSetAttribute(gemm_tc<false, false, false>,
                         cudaFuncAttributeMaxDynamicSharedMemorySize, GEMM_SMEM);
    cudaFuncSetAttribute(gemm_tc<false, true, false>,
                         cudaFuncAttributeMaxDynamicSharedMemorySize, GEMM_SMEM);
    cudaFuncSetAttribute(gemm_tc<true, false, true>,
                         cudaFuncAttributeMaxDynamicSharedMemorySize, GEMM_SMEM);

    // Weight transpose + split (each launch; deterministic)
    {
        dim3 blk(32, 8);
        dim3 gcc(C_ / 32, C_ / 32, L_);
        transpose_split_kernel<<<gcc, blk>>>(wq, wqT_h, wqT_l, C_, C_);
        transpose_split_kernel<<<gcc, blk>>>(wk, wkT_h, wkT_l, C_, C_);
        transpose_split_kernel<<<gcc, blk>>>(wv, wvT_h, wvT_l, C_, C_);
        transpose_split_kernel<<<gcc, blk>>>(wo, woT_h, woT_l, C_, C_);
        dim3 g1(F_ / 32, C_ / 32, L_);
        transpose_split_kernel<<<g1, blk>>>(w1, w1T_h, w1T_l, C_, F_);
        dim3 g2(C_ / 32, F_ / 32, L_);
        transpose_split_kernel<<<g2, blk>>>(w2, w2T_h, w2T_l, F_, C_);
    }

    embed_kernel<<<BT_, 256>>>(idx, emb, pos, x);

    dim3 gemm_cc(C_ / 128, BT_ / 128);   // (8, 32)
    dim3 gemm_cf(F_ / 128, BT_ / 128);   // (32, 32)
    dim3 attn_grid(T_ / 4, H_, B_);

    for (int l = 0; l < L_; l++) {
        layernorm_bf16_kernel<<<BT_, 256>>>(x, ln1_g + l * C_, ln1_b + l * C_, h_h, h_l);

        gemm_tc<false, false, false><<<gemm_cc, 256, GEMM_SMEM>>>(
            h_h, h_l, wqT_h + (size_t)l * C_ * C_, wqT_l + (size_t)l * C_ * C_,
            bq + l * C_, nullptr, q, nullptr, nullptr, BT_, C_, C_);
        gemm_tc<false, false, false><<<gemm_cc, 256, GEMM_SMEM>>>(
            h_h, h_l, wkT_h + (size_t)l * C_ * C_, wkT_l + (size_t)l * C_ * C_,
            bk + l * C_, nullptr, k, nullptr, nullptr, BT_, C_, C_);
        gemm_tc<false, false, false><<<gemm_cc, 256, GEMM_SMEM>>>(
            h_h, h_l, wvT_h + (size_t)l * C_ * C_, wvT_l + (size_t)l * C_ * C_,
            bv + l * C_, nullptr, v, nullptr, nullptr, BT_, C_, C_);

        attention_kernel<<<attn_grid, 128>>>(q, k, v, ao_h, ao_l);

        // x = x + (ao @ wo + bo)
        gemm_tc<false, true, false><<<gemm_cc, 256, GEMM_SMEM>>>(
            ao_h, ao_l, woT_h + (size_t)l * C_ * C_, woT_l + (size_t)l * C_ * C_,
            bo + l * C_, x, x, nullptr, nullptr, BT_, C_, C_);

        layernorm_bf16_kernel<<<BT_, 256>>>(x, ln2_g + l * C_, ln2_b + l * C_, h_h, h_l);

        // hid = relu(h @ w1 + b1)  -> bf16 hi/lo
        gemm_tc<true, false, true><<<gemm_cf, 256, GEMM_SMEM>>>(
            h_h, h_l, w1T_h + (size_t)l * C_ * F_, w1T_l + (size_t)l * C_ * F_,
            b1 + l * F_, nullptr, nullptr, hid_h, hid_l, BT_, F_, C_);
        // x = x + (hid @ w2 + b2)
        gemm_tc<false, true, false><<<gemm_cc, 256, GEMM_SMEM>>>(
            hid_h, hid_l, w2T_h + (size_t)l * F_ * C_, w2T_l + (size_t)l * F_ * C_,
            b2 + l * C_, x, x, nullptr, nullptr, BT_, C_, F_);
    }

    layernorm_last_kernel<<<B_, 256>>>(x, lnf_g, lnf_b, xf);
    logits_kernel<<<dim3(V_ / 128, B_), 128>>>(xf, out_w, out_b, out);
}

// round 6
// speedup vs baseline: 5.1351x; 2.6457x over previous
#include <cuda_runtime.h>
#include <cuda_bf16.h>
#include <float.h>
#include <cstdint>

// Problem constants
#define V_   32000
#define C_   1024
#define H_   16
#define L_   8
#define F_   4096
#define B_   2
#define T_   2048
#define D_   64
#define BT_  (B_*T_)

// ===========================================================================
// helpers
// ===========================================================================
__device__ __forceinline__ uint32_t smem_u32(const void* p) {
    uint32_t a;
    asm("{ .reg .u64 t; cvta.to.shared.u64 t, %1; cvt.u32.u64 %0, t; }"
        : "=r"(a) : "l"(p));
    return a;
}

#define CP_ASYNC16(saddr, gptr) \
    asm volatile("cp.async.cg.shared.global [%0], [%1], 16;" \
                 :: "r"(saddr), "l"(gptr) : "memory")
#define CP_COMMIT() asm volatile("cp.async.commit_group;" ::: "memory")
#define CP_WAIT1()  asm volatile("cp.async.wait_group 1;" ::: "memory")
#define CP_WAIT0()  asm volatile("cp.async.wait_group 0;" ::: "memory")

__device__ __forceinline__ void ldm_x4(uint32_t addr, uint32_t& r0, uint32_t& r1,
                                       uint32_t& r2, uint32_t& r3) {
    asm volatile("ldmatrix.sync.aligned.m8n8.x4.shared.b16 {%0,%1,%2,%3}, [%4];"
                 : "=r"(r0), "=r"(r1), "=r"(r2), "=r"(r3) : "r"(addr));
}

__device__ __forceinline__ void mma_bf16(float& d0, float& d1, float& d2, float& d3,
                                         uint32_t a0, uint32_t a1, uint32_t a2, uint32_t a3,
                                         uint32_t b0, uint32_t b1) {
    asm volatile(
        "mma.sync.aligned.m16n8k16.row.col.f32.bf16.bf16.f32 "
        "{%0,%1,%2,%3}, {%4,%5,%6,%7}, {%8,%9}, {%0,%1,%2,%3};"
        : "+f"(d0), "+f"(d1), "+f"(d2), "+f"(d3)
        : "r"(a0), "r"(a1), "r"(a2), "r"(a3), "r"(b0), "r"(b1));
}

// bf16 hi/lo split helpers
__device__ __forceinline__ void split1(float v, __nv_bfloat16& h, __nv_bfloat16& l) {
    h = __float2bfloat16(v);
    l = __float2bfloat16(v - __bfloat162float(h));
}
__device__ __forceinline__ void split2_store(float x, float y,
                                             __nv_bfloat16* ph, __nv_bfloat16* pl) {
    __nv_bfloat16 h0, h1, l0, l1;
    split1(x, h0, l0); split1(y, h1, l1);
    __nv_bfloat162 H; H.x = h0; H.y = h1;
    __nv_bfloat162 L; L.x = l0; L.y = l1;
    *(__nv_bfloat162*)ph = H;
    *(__nv_bfloat162*)pl = L;
}
__device__ __forceinline__ void split4_store(float4 v, __nv_bfloat16* ph, __nv_bfloat16* pl) {
    split2_store(v.x, v.y, ph, pl);
    split2_store(v.z, v.w, ph + 2, pl + 2);
}
// pack two floats into bf16x2 hi-word and lo-word fragments
__device__ __forceinline__ void pack_split(float x, float y, uint32_t& hi, uint32_t& lo) {
    __nv_bfloat16 hx, lx, hy, ly;
    split1(x, hx, lx); split1(y, hy, ly);
    __nv_bfloat162 Hh; Hh.x = hx; Hh.y = hy;
    __nv_bfloat162 Ll; Ll.x = lx; Ll.y = ly;
    hi = *reinterpret_cast<uint32_t*>(&Hh);
    lo = *reinterpret_cast<uint32_t*>(&Ll);
}

// ===========================================================================
// Scratch (static device arrays)
// ===========================================================================
__device__ float g_x  [BT_ * C_];
__device__ float g_v  [BT_ * C_];
__device__ float g_xf [B_ * C_];

__device__ __nv_bfloat16 g_h_h  [BT_ * C_];
__device__ __nv_bfloat16 g_h_l  [BT_ * C_];
__device__ __nv_bfloat16 g_qh   [BT_ * C_];
__device__ __nv_bfloat16 g_ql   [BT_ * C_];
__device__ __nv_bfloat16 g_kh   [BT_ * C_];
__device__ __nv_bfloat16 g_kl   [BT_ * C_];
__device__ __nv_bfloat16 g_vth  [B_ * H_ * D_ * T_];
__device__ __nv_bfloat16 g_vtl  [B_ * H_ * D_ * T_];
__device__ __nv_bfloat16 g_ao_h [BT_ * C_];
__device__ __nv_bfloat16 g_ao_l [BT_ * C_];
__device__ __nv_bfloat16 g_hid_h[BT_ * F_];
__device__ __nv_bfloat16 g_hid_l[BT_ * F_];

// transposed+split weights [N,K] bf16
__device__ __nv_bfloat16 g_wqT_h[L_ * C_ * C_];
__device__ __nv_bfloat16 g_wqT_l[L_ * C_ * C_];
__device__ __nv_bfloat16 g_wkT_h[L_ * C_ * C_];
__device__ __nv_bfloat16 g_wkT_l[L_ * C_ * C_];
__device__ __nv_bfloat16 g_wvT_h[L_ * C_ * C_];
__device__ __nv_bfloat16 g_wvT_l[L_ * C_ * C_];
__device__ __nv_bfloat16 g_woT_h[L_ * C_ * C_];
__device__ __nv_bfloat16 g_woT_l[L_ * C_ * C_];
__device__ __nv_bfloat16 g_w1T_h[L_ * C_ * F_];
__device__ __nv_bfloat16 g_w1T_l[L_ * C_ * F_];
__device__ __nv_bfloat16 g_w2T_h[L_ * F_ * C_];
__device__ __nv_bfloat16 g_w2T_l[L_ * F_ * C_];

// ===========================================================================
// Embedding
// ===========================================================================
__global__ void embed_kernel(const int* __restrict__ idx,
                             const float* __restrict__ emb,
                             const float* __restrict__ pos,
                             float* __restrict__ x) {
    int row = blockIdx.x;
    int t   = row % T_;
    int tok = idx[row];
    int c   = threadIdx.x * 4;
    float4 e = *(const float4*)(emb + (size_t)tok * C_ + c);
    float4 p = *(const float4*)(pos + (size_t)t   * C_ + c);
    float4 o;
    o.x = e.x + p.x; o.y = e.y + p.y; o.z = e.z + p.z; o.w = e.w + p.w;
    *(float4*)(x + (size_t)row * C_ + c) = o;
}

// ===========================================================================
// Weight transpose + bf16 split: in [K,N] fp32 (per layer) -> out [N,K] hi/lo
// ===========================================================================
__global__ void transpose_split_kernel(const float* __restrict__ in,
                                       __nv_bfloat16* __restrict__ oh,
                                       __nv_bfloat16* __restrict__ ol,
                                       int K, int N) {
    __shared__ float t[32][33];
    const size_t lbase = (size_t)blockIdx.z * K * N;
    const float* inl = in + lbase;
    const int k0 = blockIdx.y * 32;
    const int n0 = blockIdx.x * 32;
    #pragma unroll
    for (int j = 0; j < 4; j++) {
        int k = k0 + threadIdx.y + j * 8;
        t[threadIdx.y + j * 8][threadIdx.x] = inl[(size_t)k * N + n0 + threadIdx.x];
    }
    __syncthreads();
    #pragma unroll
    for (int j = 0; j < 4; j++) {
        int n = n0 + threadIdx.y + j * 8;
        float v = t[threadIdx.x][threadIdx.y + j * 8];
        __nv_bfloat16 h, l;
        split1(v, h, l);
        size_t off = lbase + (size_t)n * K + k0 + threadIdx.x;
        oh[off] = h;
        ol[off] = l;
    }
}

// ===========================================================================
// V transpose + split: v[BT][C] fp32 -> vt[(b*H+h)*D + d][T] bf16 hi/lo
// grid (T/32, D/32, B*H), block (32, 8)
// ===========================================================================
__global__ void v_transpose_split_kernel(const float* __restrict__ v,
                                         __nv_bfloat16* __restrict__ vth,
                                         __nv_bfloat16* __restrict__ vtl) {
    __shared__ float tile[32][33];
    const int bh = blockIdx.z;
    const int b  = bh >> 4;
    const int h  = bh & 15;
    const int t0 = blockIdx.x * 32;
    const int d0 = blockIdx.y * 32;
    const int tx = threadIdx.x, ty = threadIdx.y;
    #pragma unroll
    for (int j = 0; j < 4; j++) {
        int t = t0 + ty + j * 8;
        tile[ty + j * 8][tx] = v[(size_t)(b * T_ + t) * C_ + h * 64 + d0 + tx];
    }
    __syncthreads();
    #pragma unroll
    for (int j = 0; j < 4; j++) {
        int d = d0 + ty + j * 8;
        float val = tile[tx][ty + j * 8];
        __nv_bfloat16 hh, ll;
        split1(val, hh, ll);
        size_t off = ((size_t)bh * 64 + d) * T_ + t0 + tx;
        vth[off] = hh;
        vtl[off] = ll;
    }
}

// ===========================================================================
// LayerNorm, bf16 hi/lo output. 1 row/block, 256 threads.
// ===========================================================================
__global__ void layernorm_bf16_kernel(const float* __restrict__ x,
                                      const float* __restrict__ g,
                                      const float* __restrict__ b,
                                      __nv_bfloat16* __restrict__ yh,
                                      __nv_bfloat16* __restrict__ yl) {
    int row = blockIdx.x;
    int tid = threadIdx.x;
    int c = tid * 4;

    float4 xv = *(const float4*)(x + (size_t)row * C_ + c);
    float s  = xv.x + xv.y + xv.z + xv.w;
    float sq = xv.x*xv.x + xv.y*xv.y + xv.z*xv.z + xv.w*xv.w;

    __shared__ float ssum[256];
    __shared__ float ssq[256];
    ssum[tid] = s; ssq[tid] = sq;
    __syncthreads();
    #pragma unroll
    for (int st = 128; st > 0; st >>= 1) {
        if (tid < st) { ssum[tid] += ssum[tid+st]; ssq[tid] += ssq[tid+st]; }
        __syncthreads();
    }
    __shared__ float s_mean, s_rstd;
    if (tid == 0) {
        float mean = ssum[0] * (1.0f / C_);
        float var  = ssq[0] * (1.0f / C_) - mean * mean;
        s_mean = mean;
        s_rstd = rsqrtf(var + 1e-5f);
    }
    __syncthreads();
    float mean = s_mean, rstd = s_rstd;

    float4 gv = *(const float4*)(g + c);
    float4 bv = *(const float4*)(b + c);
    float4 o;
    o.x = (xv.x - mean) * rstd * gv.x + bv.x;
    o.y = (xv.y - mean) * rstd * gv.y + bv.y;
    o.z = (xv.z - mean) * rstd * gv.z + bv.z;
    o.w = (xv.w - mean) * rstd * gv.w + bv.w;
    split4_store(o, yh + (size_t)row * C_ + c, yl + (size_t)row * C_ + c);
}

// Final LayerNorm (last token), fp32 output
__global__ void layernorm_last_kernel(const float* __restrict__ x,
                                      const float* __restrict__ g,
                                      const float* __restrict__ b,
                                      float* __restrict__ y) {
    int row_in  = blockIdx.x * T_ + (T_ - 1);
    int tid = threadIdx.x;
    int c = tid * 4;

    float4 xv = *(const float4*)(x + (size_t)row_in * C_ + c);
    float s  = xv.x + xv.y + xv.z + xv.w;
    float sq = xv.x*xv.x + xv.y*xv.y + xv.z*xv.z + xv.w*xv.w;

    __shared__ float ssum[256];
    __shared__ float ssq[256];
    ssum[tid] = s; ssq[tid] = sq;
    __syncthreads();
    #pragma unroll
    for (int st = 128; st > 0; st >>= 1) {
        if (tid < st) { ssum[tid] += ssum[tid+st]; ssq[tid] += ssq[tid+st]; }
        __syncthreads();
    }
    __shared__ float s_mean, s_rstd;
    if (tid == 0) {
        float mean = ssum[0] * (1.0f / C_);
        float var  = ssq[0] * (1.0f / C_) - mean * mean;
        s_mean = mean;
        s_rstd = rsqrtf(var + 1e-5f);
    }
    __syncthreads();
    float mean = s_mean, rstd = s_rstd;

    float4 gv = *(const float4*)(g + c);
    float4 bv = *(const float4*)(b + c);
    float4 o;
    o.x = (xv.x - mean) * rstd * gv.x + bv.x;
    o.y = (xv.y - mean) * rstd * gv.y + bv.y;
    o.z = (xv.z - mean) * rstd * gv.z + bv.z;
    o.w = (xv.w - mean) * rstd * gv.w + bv.w;
    *(float4*)(y + (size_t)blockIdx.x * C_ + c) = o;
}

// ===========================================================================
// mma.sync split-bf16 GEMM (unchanged from R4, validated).
// ===========================================================================
#define SWZ(row, chunk) ((((chunk) ^ ((row) & 7)) << 4) + (row) * 128)
#define TILE_BYTES   16384
#define STAGE_BYTES  (4 * TILE_BYTES)
#define GEMM_SMEM    (2 * STAGE_BYTES)

__device__ __forceinline__ void load_tile_cp(const __nv_bfloat16* __restrict__ src,
                                             int row0, int K, int kt,
                                             uint32_t sbase, int tid) {
    #pragma unroll
    for (int r = 0; r < 4; r++) {
        int cid = tid + r * 256;
        int row = cid >> 3;
        int c   = cid & 7;
        const __nv_bfloat16* g = src + (size_t)(row0 + row) * K + kt * 64 + c * 8;
        CP_ASYNC16(sbase + SWZ(row, c), g);
    }
}

template<bool RELU, bool RES, bool OUTBF16>
__global__ __launch_bounds__(256, 1)
void gemm_tc(const __nv_bfloat16* __restrict__ Ah, const __nv_bfloat16* __restrict__ Al,
             const __nv_bfloat16* __restrict__ Bh, const __nv_bfloat16* __restrict__ Bl,
             const float* __restrict__ bias, const float* __restrict__ res,
             float* __restrict__ Cf,
             __nv_bfloat16* __restrict__ Ch, __nv_bfloat16* __restrict__ Cl,
             int M, int N, int K) {
    extern __shared__ char dsm[];
    const uint32_t base = smem_u32(dsm);

    const int tid  = threadIdx.x;
    const int wid  = tid >> 5;
    const int lane = tid & 31;
    const int m0 = blockIdx.y * 128;
    const int n0 = blockIdx.x * 128;
    const int wm = wid & 1;
    const int wn = wid >> 1;

    float acc[4][4][4];
    #pragma unroll
    for (int i = 0; i < 4; i++)
        #pragma unroll
        for (int j = 0; j < 4; j++)
            #pragma unroll
            for (int r = 0; r < 4; r++) acc[i][j][r] = 0.0f;

    const int nkt = K >> 6;

    const int a_row  = wm * 64 + (lane & 15);
    const int a_csel = lane >> 4;
    const int b_row  = wn * 32 + ((lane & 7) | ((lane & 16) >> 1));
    const int b_csel = (lane >> 3) & 1;

    load_tile_cp(Ah, m0, K, 0, base,                   tid);
    load_tile_cp(Al, m0, K, 0, base + TILE_BYTES,      tid);
    load_tile_cp(Bh, n0, K, 0, base + 2 * TILE_BYTES,  tid);
    load_tile_cp(Bl, n0, K, 0, base + 3 * TILE_BYTES,  tid);
    CP_COMMIT();
    if (nkt > 1) {
        load_tile_cp(Ah, m0, K, 1, base + STAGE_BYTES,                  tid);
        load_tile_cp(Al, m0, K, 1, base + STAGE_BYTES + TILE_BYTES,     tid);
        load_tile_cp(Bh, n0, K, 1, base + STAGE_BYTES + 2 * TILE_BYTES, tid);
        load_tile_cp(Bl, n0, K, 1, base + STAGE_BYTES + 3 * TILE_BYTES, tid);
        CP_COMMIT();
    }

    for (int kt = 0; kt < nkt; kt++) {
        if (kt + 1 < nkt) { CP_WAIT1(); } else { CP_WAIT0(); }
        __syncthreads();

        const uint32_t sb  = base + (kt & 1) * STAGE_BYTES;
        const uint32_t sAh = sb;
        const uint32_t sAl = sb + TILE_BYTES;
        const uint32_t sBh = sb + 2 * TILE_BYTES;
        const uint32_t sBl = sb + 3 * TILE_BYTES;

        #pragma unroll
        for (int ks = 0; ks < 4; ks++) {
            const int ac = ks * 2 + a_csel;
            const int bc = ks * 2 + b_csel;
            uint32_t ah[4][4], al[4][4];
            #pragma unroll
            for (int mi = 0; mi < 4; mi++) {
                int row = a_row + mi * 16;
                ldm_x4(sAh + SWZ(row, ac), ah[mi][0], ah[mi][1], ah[mi][2], ah[mi][3]);
                ldm_x4(sAl + SWZ(row, ac), al[mi][0], al[mi][1], al[mi][2], al[mi][3]);
            }
            uint32_t bh[4][2], bl[4][2];
            #pragma unroll
            for (int nj = 0; nj < 2; nj++) {
                int row = b_row + nj * 16;
                ldm_x4(sBh + SWZ(row, bc), bh[nj*2][0], bh[nj*2][1], bh[nj*2+1][0], bh[nj*2+1][1]);
                ldm_x4(sBl + SWZ(row, bc), bl[nj*2][0], bl[nj*2][1], bl[nj*2+1][0], bl[nj*2+1][1]);
            }
            #pragma unroll
            for (int mi = 0; mi < 4; mi++) {
                #pragma unroll
                for (int ni = 0; ni < 4; ni++) {
                    mma_bf16(acc[mi][ni][0], acc[mi][ni][1], acc[mi][ni][2], acc[mi][ni][3],
                             ah[mi][0], ah[mi][1], ah[mi][2], ah[mi][3],
                             bh[ni][0], bh[ni][1]);
                    mma_bf16(acc[mi][ni][0], acc[mi][ni][1], acc[mi][ni][2], acc[mi][ni][3],
                             ah[mi][0], ah[mi][1], ah[mi][2], ah[mi][3],
                             bl[ni][0], bl[ni][1]);
                    mma_bf16(acc[mi][ni][0], acc[mi][ni][1], acc[mi][ni][2], acc[mi][ni][3],
                             al[mi][0], al[mi][1], al[mi][2], al[mi][3],
                             bh[ni][0], bh[ni][1]);
                }
            }
        }
        __syncthreads();
        if (kt + 2 < nkt) {
            const uint32_t nb = base + (kt & 1) * STAGE_BYTES;
            load_tile_cp(Ah, m0, K, kt + 2, nb,                  tid);
            load_tile_cp(Al, m0, K, kt + 2, nb + TILE_BYTES,     tid);
            load_tile_cp(Bh, n0, K, kt + 2, nb + 2 * TILE_BYTES, tid);
            load_tile_cp(Bl, n0, K, kt + 2, nb + 3 * TILE_BYTES, tid);
            CP_COMMIT();
        }
    }

    const int qm = lane >> 2;
    const int qn = (lane & 3) * 2;
    #pragma unroll
    for (int mi = 0; mi < 4; mi++) {
        #pragma unroll
        for (int ni = 0; ni < 4; ni++) {
            const int n = n0 + wn * 32 + ni * 8 + qn;
            float2 bv = *(const float2*)(bias + n);
            #pragma unroll
            for (int half = 0; half < 2; half++) {
                const int m = m0 + wm * 64 + mi * 16 + qm + half * 8;
                float vx = acc[mi][ni][half*2 + 0] + bv.x;
                float vy = acc[mi][ni][half*2 + 1] + bv.y;
                if (RELU) { vx = fmaxf(vx, 0.f); vy = fmaxf(vy, 0.f); }
                if (RES) {
                    float2 rv = *(const float2*)(res + (size_t)m * N + n);
                    vx += rv.x; vy += rv.y;
                }
                if (OUTBF16) {
                    split2_store(vx, vy, Ch + (size_t)m * N + n, Cl + (size_t)m * N + n);
                } else {
                    *(float2*)(Cf + (size_t)m * N + n) = make_float2(vx, vy);
                }
            }
        }
    }
}

// ===========================================================================
// Tensor-core flash attention: 64 queries/block, 64-key tiles, 4 warps.
// Split-bf16 3-term mma for QK^T and P·V. fp32 softmax/accumulators.
// Q,K in [BT][C] bf16 hi/lo; V^T in [(b*H+h)*64+d][T] bf16 hi/lo.
// ===========================================================================
#define ATT_SMEM (16384 + 32768)

__global__ __launch_bounds__(128)
void attention_mma_kernel(const __nv_bfloat16* __restrict__ Qh, const __nv_bfloat16* __restrict__ Ql,
                          const __nv_bfloat16* __restrict__ Kh, const __nv_bfloat16* __restrict__ Kl,
                          const __nv_bfloat16* __restrict__ Vth, const __nv_bfloat16* __restrict__ Vtl,
                          __nv_bfloat16* __restrict__ aoh, __nv_bfloat16* __restrict__ aol) {
    extern __shared__ char dsm[];
    const uint32_t base = smem_u32(dsm);
    const uint32_t sQh = base;
    const uint32_t sQl = base + 8192;
    const uint32_t sKh = base + 16384;
    const uint32_t sKl = base + 24576;
    const uint32_t sVh = base + 32768;
    const uint32_t sVl = base + 40960;

    const int b  = blockIdx.z;
    const int h  = blockIdx.y;
    const int qt = (T_ / 64 - 1) - blockIdx.x;   // longest blocks first
    const int tid  = threadIdx.x;
    const int wid  = tid >> 5;
    const int lane = tid & 31;
    const int m_base = wid * 16;

    // ---- stage Q (hi+lo) ----
    #pragma unroll
    for (int r = 0; r < 4; r++) {
        int cid = tid + r * 128;      // 0..511
        int row = cid >> 3;
        int c   = cid & 7;
        size_t goff = (size_t)(b * T_ + qt * 64 + row) * C_ + h * 64 + c * 8;
        CP_ASYNC16(sQh + SWZ(row, c), Qh + goff);
        CP_ASYNC16(sQl + SWZ(row, c), Ql + goff);
    }
    CP_COMMIT(); CP_WAIT0();
    __syncthreads();

    // ---- Q fragments to registers ----
    const int a_row  = m_base + (lane & 15);
    const int a_csel = lane >> 4;
    uint32_t qfh[4][4], qfl[4][4];
    #pragma unroll
    for (int ks = 0; ks < 4; ks++) {
        ldm_x4(sQh + SWZ(a_row, ks*2 + a_csel), qfh[ks][0], qfh[ks][1], qfh[ks][2], qfh[ks][3]);
        ldm_x4(sQl + SWZ(a_row, ks*2 + a_csel), qfl[ks][0], qfl[ks][1], qfl[ks][2], qfl[ks][3]);
    }

    const int b_row_l = (lane & 7) | ((lane & 16) >> 1);
    const int b_csel  = (lane >> 3) & 1;
    const int qm = lane >> 2;
    const int qn = (lane & 3) * 2;

    float o[8][4];
    #pragma unroll
    for (int n = 0; n < 8; n++)
        #pragma unroll
        for (int r = 0; r < 4; r++) o[n][r] = 0.0f;
    float mrow[2] = {-FLT_MAX, -FLT_MAX};
    float lrow[2] = {0.0f, 0.0f};

    for (int kt = 0; kt <= qt; kt++) {
        __syncthreads();   // previous tile fully consumed
        #pragma unroll
        for (int r = 0; r < 4; r++) {
            int cid = tid + r * 128;
            int row = cid >> 3;
            int c   = cid & 7;
            size_t koff = (size_t)(b * T_ + kt * 64 + row) * C_ + h * 64 + c * 8;
            size_t voff = ((size_t)(b * H_ + h) * 64 + row) * T_ + kt * 64 + c * 8;
            CP_ASYNC16(sKh + SWZ(row, c), Kh + koff);
            CP_ASYNC16(sKl + SWZ(row, c), Kl + koff);
            CP_ASYNC16(sVh + SWZ(row, c), Vth + voff);
            CP_ASYNC16(sVl + SWZ(row, c), Vtl + voff);
        }
        CP_COMMIT(); CP_WAIT0();
        __syncthreads();

        // ---- scores S = 3-term Q K^T ----
        float sc[8][4];
        #pragma unroll
        for (int n = 0; n < 8; n++)
            #pragma unroll
            for (int r = 0; r < 4; r++) sc[n][r] = 0.0f;

        #pragma unroll
        for (int ks = 0; ks < 4; ks++) {
            const int bc = ks * 2 + b_csel;
            #pragma unroll
            for (int g = 0; g < 4; g++) {
                uint32_t r0, r1, r2, r3, s0, s1, s2, s3;
                ldm_x4(sKh + SWZ(g * 16 + b_row_l, bc), r0, r1, r2, r3);
                ldm_x4(sKl + SWZ(g * 16 + b_row_l, bc), s0, s1, s2, s3);
                mma_bf16(sc[2*g][0], sc[2*g][1], sc[2*g][2], sc[2*g][3],
                         qfh[ks][0], qfh[ks][1], qfh[ks][2], qfh[ks][3], r0, r1);
                mma_bf16(sc[2*g+1][0], sc[2*g+1][1], sc[2*g+1][2], sc[2*g+1][3],
                         qfh[ks][0], qfh[ks][1], qfh[ks][2], qfh[ks][3], r2, r3);
                mma_bf16(sc[2*g][0], sc[2*g][1], sc[2*g][2], sc[2*g][3],
                         qfh[ks][0], qfh[ks][1], qfh[ks][2], qfh[ks][3], s0, s1);
                mma_bf16(sc[2*g+1][0], sc[2*g+1][1], sc[2*g+1][2], sc[2*g+1][3],
                         qfh[ks][0], qfh[ks][1], qfh[ks][2], qfh[ks][3], s2, s3);
                mma_bf16(sc[2*g][0], sc[2*g][1], sc[2*g][2], sc[2*g][3],
                         qfl[ks][0], qfl[ks][1], qfl[ks][2], qfl[ks][3], r0, r1);
                mma_bf16(sc[2*g+1][0], sc[2*g+1][1], sc[2*g+1][2], sc[2*g+1][3],
                         qfl[ks][0], qfl[ks][1], qfl[ks][2], qfl[ks][3], r2, r3);
            }
        }

        // scale
        #pragma unroll
        for (int n = 0; n < 8; n++)
            #pragma unroll
            for (int r = 0; r < 4; r++) sc[n][r] *= 0.125f;

        // causal mask on diagonal tile
        if (kt == qt) {
            const int row0 = m_base + qm;
            const int row1 = row0 + 8;
            #pragma unroll
            for (int n = 0; n < 8; n++) {
                int col = n * 8 + qn;
                if (col     > row0) sc[n][0] = -FLT_MAX;
                if (col + 1 > row0) sc[n][1] = -FLT_MAX;
                if (col     > row1) sc[n][2] = -FLT_MAX;
                if (col + 1 > row1) sc[n][3] = -FLT_MAX;
            }
        }

        // ---- online softmax (two rows per thread) ----
        #pragma unroll
        for (int r = 0; r < 2; r++) {
            float mx = -FLT_MAX;
            #pragma unroll
            for (int n = 0; n < 8; n++) {
                mx = fmaxf(mx, sc[n][2*r]);
                mx = fmaxf(mx, sc[n][2*r + 1]);
            }
            mx = fmaxf(mx, __shfl_xor_sync(0xffffffffu, mx, 1));
            mx = fmaxf(mx, __shfl_xor_sync(0xffffffffu, mx, 2));
            float mnew = fmaxf(mrow[r], mx);
            float alpha = __expf(mrow[r] - mnew);
            float sum = 0.0f;
            #pragma unroll
            for (int n = 0; n < 8; n++) {
                float p0 = __expf(sc[n][2*r]     - mnew);
                float p1 = __expf(sc[n][2*r + 1] - mnew);
                sc[n][2*r]     = p0;
                sc[n][2*r + 1] = p1;
                sum += p0 + p1;
            }
            sum += __shfl_xor_sync(0xffffffffu, sum, 1);
            sum += __shfl_xor_sync(0xffffffffu, sum, 2);
            lrow[r] = lrow[r] * alpha + sum;
            mrow[r] = mnew;
            #pragma unroll
            for (int n = 0; n < 8; n++) {
                o[n][2*r]     *= alpha;
                o[n][2*r + 1] *= alpha;
            }
        }

        // ---- O += 3-term P V ----
        #pragma unroll
        for (int ks = 0; ks < 4; ks++) {
            uint32_t ph0, ph1, ph2, ph3, pl0, pl1, pl2, pl3;
            pack_split(sc[2*ks][0],   sc[2*ks][1],   ph0, pl0);
            pack_split(sc[2*ks][2],   sc[2*ks][3],   ph1, pl1);
            pack_split(sc[2*ks+1][0], sc[2*ks+1][1], ph2, pl2);
            pack_split(sc[2*ks+1][2], sc[2*ks+1][3], ph3, pl3);
            const int bc = ks * 2 + b_csel;
            #pragma unroll
            for (int g = 0; g < 4; g++) {
                uint32_t r0, r1, r2, r3, s0, s1, s2, s3;
                ldm_x4(sVh + SWZ(g * 16 + b_row_l, bc), r0, r1, r2, r3);
                ldm_x4(sVl + SWZ(g * 16 + b_row_l, bc), s0, s1, s2, s3);
                mma_bf16(o[2*g][0], o[2*g][1], o[2*g][2], o[2*g][3],
                         ph0, ph1, ph2, ph3, r0, r1);
                mma_bf16(o[2*g+1][0], o[2*g+1][1], o[2*g+1][2], o[2*g+1][3],
                         ph0, ph1, ph2, ph3, r2, r3);
                mma_bf16(o[2*g][0], o[2*g][1], o[2*g][2], o[2*g][3],
                         ph0, ph1, ph2, ph3, s0, s1);
                mma_bf16(o[2*g+1][0], o[2*g+1][1], o[2*g+1][2], o[2*g+1][3],
                         ph0, ph1, ph2, ph3, s2, s3);
                mma_bf16(o[2*g][0], o[2*g][1], o[2*g][2], o[2*g][3],
                         pl0, pl1, pl2, pl3, r0, r1);
                mma_bf16(o[2*g+1][0], o[2*g+1][1], o[2*g+1][2], o[2*g+1][3],
                         pl0, pl1, pl2, pl3, r2, r3);
            }
        }
    }

    // ---- normalize and store (bf16 hi/lo) ----
    const float inv0 = 1.0f / lrow[0];
    const float inv1 = 1.0f / lrow[1];
    const size_t row0 = (size_t)(b * T_ + qt * 64 + m_base + qm) * C_;
    const size_t row1 = row0 + 8 * C_;
    #pragma unroll
    for (int n = 0; n < 8; n++) {
        int col = h * 64 + n * 8 + qn;
        split2_store(o[n][0] * inv0, o[n][1] * inv0, aoh + row0 + col, aol + row0 + col);
        split2_store(o[n][2] * inv1, o[n][3] * inv1, aoh + row1 + col, aol + row1 + col);
    }
}

// ===========================================================================
// Logits
// ===========================================================================
__global__ void logits_kernel(const float* __restrict__ xf,
                              const float* __restrict__ W,
                              const float* __restrict__ bias,
                              float* __restrict__ out) {
    __shared__ float xs[C_];
    const int b = blockIdx.y;
    const int tid = threadIdx.x;
    #pragma unroll
    for (int r = 0; r < C_ / 128; r++)
        xs[tid + r * 128] = xf[b * C_ + tid + r * 128];
    __syncthreads();

    int vcol = blockIdx.x * 128 + tid;
    float acc = bias[vcol];
    const float* wp = W + vcol;
    #pragma unroll 8
    for (int k = 0; k < C_; k++)
        acc = fmaf(xs[k], wp[(size_t)k * V_], acc);
    out[(size_t)b * V_ + vcol] = acc;
}

// ===========================================================================
// Launch
// ===========================================================================
extern "C" void kernel_launch(void* const* d_in, const int* in_sizes, int n_in,
                              void* d_out, int out_size) {
    const int*   idx   = (const int*)  d_in[0];
    const float* emb   = (const float*)d_in[1];
    const float* pos   = (const float*)d_in[2];
    const float* ln1_g = (const float*)d_in[3];
    const float* ln1_b = (const float*)d_in[4];
    const float* wq    = (const float*)d_in[5];
    const float* bq    = (const float*)d_in[6];
    const float* wk    = (const float*)d_in[7];
    const float* bk    = (const float*)d_in[8];
    const float* wv    = (const float*)d_in[9];
    const float* bv    = (const float*)d_in[10];
    const float* wo    = (const float*)d_in[11];
    const float* bo    = (const float*)d_in[12];
    const float* ln2_g = (const float*)d_in[13];
    const float* ln2_b = (const float*)d_in[14];
    const float* w1    = (const float*)d_in[15];
    const float* b1    = (const float*)d_in[16];
    const float* w2    = (const float*)d_in[17];
    const float* b2    = (const float*)d_in[18];
    const float* lnf_g = (const float*)d_in[19];
    const float* lnf_b = (const float*)d_in[20];
    const float* out_w = (const float*)d_in[21];
    const float* out_b = (const float*)d_in[22];
    float* out = (float*)d_out;

    float *x, *v, *xf;
    cudaGetSymbolAddress((void**)&x,  g_x);
    cudaGetSymbolAddress((void**)&v,  g_v);
    cudaGetSymbolAddress((void**)&xf, g_xf);

    __nv_bfloat16 *h_h, *h_l, *qh, *ql, *kh, *kl, *vth, *vtl, *ao_h, *ao_l, *hid_h, *hid_l;
    cudaGetSymbolAddress((void**)&h_h,   g_h_h);
    cudaGetSymbolAddress((void**)&h_l,   g_h_l);
    cudaGetSymbolAddress((void**)&qh,    g_qh);
    cudaGetSymbolAddress((void**)&ql,    g_ql);
    cudaGetSymbolAddress((void**)&kh,    g_kh);
    cudaGetSymbolAddress((void**)&kl,    g_kl);
    cudaGetSymbolAddress((void**)&vth,   g_vth);
    cudaGetSymbolAddress((void**)&vtl,   g_vtl);
    cudaGetSymbolAddress((void**)&ao_h,  g_ao_h);
    cudaGetSymbolAddress((void**)&ao_l,  g_ao_l);
    cudaGetSymbolAddress((void**)&hid_h, g_hid_h);
    cudaGetSymbolAddress((void**)&hid_l, g_hid_l);

    __nv_bfloat16 *wqT_h, *wqT_l, *wkT_h, *wkT_l, *wvT_h, *wvT_l, *woT_h, *woT_l;
    __nv_bfloat16 *w1T_h, *w1T_l, *w2T_h, *w2T_l;
    cudaGetSymbolAddress((void**)&wqT_h, g_wqT_h);
    cudaGetSymbolAddress((void**)&wqT_l, g_wqT_l);
    cudaGetSymbolAddress((void**)&wkT_h, g_wkT_h);
    cudaGetSymbolAddress((void**)&wkT_l, g_wkT_l);
    cudaGetSymbolAddress((void**)&wvT_h, g_wvT_h);
    cudaGetSymbolAddress((void**)&wvT_l, g_wvT_l);
    cudaGetSymbolAddress((void**)&woT_h, g_woT_h);
    cudaGetSymbolAddress((void**)&woT_l, g_woT_l);
    cudaGetSymbolAddress((void**)&w1T_h, g_w1T_h);
    cudaGetSymbolAddress((void**)&w1T_l, g_w1T_l);
    cudaGetSymbolAddress((void**)&w2T_h, g_w2T_h);
    cudaGetSymbolAddress((void**)&w2T_l, g_w2T_l);

    cudaFuncSetAttribute(gemm_tc<false, false, false>,
                         cudaFuncAttributeMaxDynamicSharedMemorySize, GEMM_SMEM);
    cudaFuncSetAttribute(gemm_tc<false, false, true>,
                         cudaFuncAttributeMaxDynamicSharedMemorySize, GEMM_SMEM);
    cudaFuncSetAttribute(gemm_tc<false, true, false>,
                         cudaFuncAttributeMaxDynamicSharedMemorySize, GEMM_SMEM);
    cudaFuncSetAttribute(gemm_tc<true, false, true>,
                         cudaFuncAttributeMaxDynamicSharedMemorySize, GEMM_SMEM);
    cudaFuncSetAttribute(attention_mma_kernel,
                         cudaFuncAttributeMaxDynamicSharedMemorySize, ATT_SMEM);

    // Weight transpose + split
    {
        dim3 blk(32, 8);
        dim3 gcc(C_ / 32, C_ / 32, L_);
        transpose_split_kernel<<<gcc, blk>>>(wq, wqT_h, wqT_l, C_, C_);
        transpose_split_kernel<<<gcc, blk>>>(wk, wkT_h, wkT_l, C_, C_);
        transpose_split_kernel<<<gcc, blk>>>(wv, wvT_h, wvT_l, C_, C_);
        transpose_split_kernel<<<gcc, blk>>>(wo, woT_h, woT_l, C_, C_);
        dim3 g1(F_ / 32, C_ / 32, L_);
        transpose_split_kernel<<<g1, blk>>>(w1, w1T_h, w1T_l, C_, F_);
        dim3 g2(C_ / 32, F_ / 32, L_);
        transpose_split_kernel<<<g2, blk>>>(w2, w2T_h, w2T_l, F_, C_);
    }

    embed_kernel<<<BT_, 256>>>(idx, emb, pos, x);

    dim3 gemm_cc(C_ / 128, BT_ / 128);   // (8, 32)
    dim3 gemm_cf(F_ / 128, BT_ / 128);   // (32, 32)
    dim3 attn_grid(T_ / 64, H_, B_);     // (32, 16, 2)
    dim3 vt_grid(T_ / 32, D_ / 32, B_ * H_);
    dim3 vt_blk(32, 8);

    for (int l = 0; l < L_; l++) {
        layernorm_bf16_kernel<<<BT_, 256>>>(x, ln1_g + l * C_, ln1_b + l * C_, h_h, h_l);

        gemm_tc<false, false, true><<<gemm_cc, 256, GEMM_SMEM>>>(
            h_h, h_l, wqT_h + (size_t)l * C_ * C_, wqT_l + (size_t)l * C_ * C_,
            bq + l * C_, nullptr, nullptr, qh, ql, BT_, C_, C_);
        gemm_tc<false, false, true><<<gemm_cc, 256, GEMM_SMEM>>>(
            h_h, h_l, wkT_h + (size_t)l * C_ * C_, wkT_l + (size_t)l * C_ * C_,
            bk + l * C_, nullptr, nullptr, kh, kl, BT_, C_, C_);
        gemm_tc<false, false, false><<<gemm_cc, 256, GEMM_SMEM>>>(
            h_h, h_l, wvT_h + (size_t)l * C_ * C_, wvT_l + (size_t)l * C_ * C_,
            bv + l * C_, nullptr, v, nullptr, nullptr, BT_, C_, C_);

        v_transpose_split_kernel<<<vt_grid, vt_blk>>>(v, vth, vtl);

        attention_mma_kernel<<<attn_grid, 128, ATT_SMEM>>>(
            qh, ql, kh, kl, vth, vtl, ao_h, ao_l);

        // x = x + (ao @ wo + bo)
        gemm_tc<false, true, false><<<gemm_cc, 256, GEMM_SMEM>>>(
            ao_h, ao_l, woT_h + (size_t)l * C_ * C_, woT_l + (size_t)l * C_ * C_,
            bo + l * C_, x, x, nullptr, nullptr, BT_, C_, C_);

        layernorm_bf16_kernel<<<BT_, 256>>>(x, ln2_g + l * C_, ln2_b + l * C_, h_h, h_l);

        // hid = relu(h @ w1 + b1)  -> bf16 hi/lo
        gemm_tc<true, false, true><<<gemm_cf, 256, GEMM_SMEM>>>(
            h_h, h_l, w1T_h + (size_t)l * C_ * F_, w1T_l + (size_t)l * C_ * F_,
            b1 + l * F_, nullptr, nullptr, hid_h, hid_l, BT_, F_, C_);
        // x = x + (hid @ w2 + b2)
        gemm_tc<false, true, false><<<gemm_cc, 256, GEMM_SMEM>>>(
            hid_h, hid_l, w2T_h + (size_t)l * F_ * C_, w2T_l + (size_t)l * F_ * C_,
            b2 + l * C_, x, x, nullptr, nullptr, BT_, C_, F_);
    }

    layernorm_last_kernel<<<B_, 256>>>(x, lnf_g, lnf_b, xf);
    logits_kernel<<<dim3(V_ / 128, B_), 128>>>(xf, out_w, out_b, out);
}